// round 15
// baseline (speedup 1.0000x reference)
#include <cuda_runtime.h>
#include <cuda_fp16.h>
#include <cstdint>

#define B 4
#define L 2048
#define DIM 512
#define H 8
#define D 64
#define M_TOTAL (B * L)
#define SCALE 0.125f
#define LOG2E 1.44269504088896f

// fp16 scratch (allocation-free rule: __device__ globals).
__device__ __half hx[M_TOTAL * DIM];
__device__ __half hw[4 * DIM * DIM];         // wq, wk, wv, wo
__device__ __half g_q[M_TOTAL * DIM];        // pre-scaled by SCALE
__device__ __half g_k[M_TOTAL * DIM];        // pre-scaled by log2(e)
__device__ __half g_v[M_TOTAL * DIM];
__device__ __half g_o[M_TOTAL * DIM];

__device__ __forceinline__ uint32_t pack2(float a, float b) {
    __half2 h = __floats2half2_rn(a, b);
    return *(uint32_t*)&h;
}
__device__ __forceinline__ uint32_t h2ex2(uint32_t x) {
    uint32_t r;
    asm("ex2.approx.f16x2 %0, %1;" : "=r"(r) : "r"(x));
    return r;
}

__device__ __forceinline__ void mma_f16(float* d, const uint32_t* a,
                                        const uint32_t* b) {
    asm volatile(
        "mma.sync.aligned.m16n8k16.row.col.f32.f16.f16.f32 "
        "{%0,%1,%2,%3}, {%4,%5,%6,%7}, {%8,%9}, {%0,%1,%2,%3};"
        : "+f"(d[0]), "+f"(d[1]), "+f"(d[2]), "+f"(d[3])
        : "r"(a[0]), "r"(a[1]), "r"(a[2]), "r"(a[3]), "r"(b[0]), "r"(b[1]));
}

__device__ __forceinline__ uint32_t smem_u32(const void* p) {
    uint32_t a;
    asm("{ .reg .u64 t; cvta.to.shared.u64 t, %1; cvt.u32.u64 %0, t; }"
        : "=r"(a) : "l"(p));
    return a;
}

#define LDSM4(d0, d1, d2, d3, a) \
    asm volatile("ldmatrix.sync.aligned.m8n8.x4.shared.b16 {%0,%1,%2,%3}, [%4];" \
                 : "=r"(d0), "=r"(d1), "=r"(d2), "=r"(d3) : "r"(a))
#define LDSM4T(d0, d1, d2, d3, a) \
    asm volatile("ldmatrix.sync.aligned.m8n8.x4.trans.shared.b16 {%0,%1,%2,%3}, [%4];" \
                 : "=r"(d0), "=r"(d1), "=r"(d2), "=r"(d3) : "r"(a))
#define LDSM2T(d0, d1, a) \
    asm volatile("ldmatrix.sync.aligned.m8n8.x2.trans.shared.b16 {%0,%1}, [%2];" \
                 : "=r"(d0), "=r"(d1) : "r"(a))

#define CP16(dst, src) \
    asm volatile("cp.async.cg.shared.global [%0], [%1], 16;" \
                 :: "r"(dst), "l"(src) : "memory")
#define CP_COMMIT() asm volatile("cp.async.commit_group;" ::: "memory")
#define CP_WAIT1() asm volatile("cp.async.wait_group 1;" ::: "memory")
#define CP_WAIT0() asm volatile("cp.async.wait_group 0;" ::: "memory")

// ---------------------------------------------------------------------------
// fp32 -> fp16 conversion, one launch (blockIdx.y selects tensor).
// ---------------------------------------------------------------------------
__global__ void cvt_all(const float* __restrict__ x,  const float* __restrict__ wq,
                        const float* __restrict__ wk, const float* __restrict__ wv,
                        const float* __restrict__ wo) {
    const int sel = blockIdx.y;
    const float* src;
    __half* dst;
    int n4;
    if (sel == 0) { src = x;  dst = hx;                 n4 = M_TOTAL * DIM / 4; }
    else if (sel == 1) { src = wq; dst = hw;                n4 = DIM * DIM / 4; }
    else if (sel == 2) { src = wk; dst = hw + DIM * DIM;    n4 = DIM * DIM / 4; }
    else if (sel == 3) { src = wv; dst = hw + 2 * DIM * DIM; n4 = DIM * DIM / 4; }
    else { src = wo; dst = hw + 3 * DIM * DIM; n4 = DIM * DIM / 4; }
    int i = blockIdx.x * blockDim.x + threadIdx.x;
    int stride = gridDim.x * blockDim.x;
    for (; i < n4; i += stride) {
        float4 v = ((const float4*)src)[i];
        ((__half2*)dst)[2 * i] = __floats2half2_rn(v.x, v.y);
        ((__half2*)dst)[2 * i + 1] = __floats2half2_rn(v.z, v.w);
    }
}

// ---------------------------------------------------------------------------
// GEMM: Y = X @ W.T, fp16 m16n8k16, f32 accum, ldmatrix, 3-stage cp.async,
// K-chunk 64 (half the sync events of K-32), single barrier per iteration,
// issue(t+2) after the barrier (3-stage safety). escale folds SCALE/log2e.
// ---------------------------------------------------------------------------
#define PADH 72                               // halves per row (144 B)
#define GST_H (2 * 128 * PADH)                // A+B halves per stage (18432)
#define GEMM_SMEM (3 * GST_H * 2)             // 110592 B -> 2 CTAs/SM

__device__ __forceinline__ void gemm_body(const __half* __restrict__ X,
                                          const __half* __restrict__ W,
                                          __half* __restrict__ Yh,
                                          float* __restrict__ Yf,
                                          float escale) {
    extern __shared__ __half smg[];
    const int tid = threadIdx.x, lane = tid & 31, wid = tid >> 5;
    const int wm = wid & 3, wn = wid >> 2;
    const int mb = blockIdx.y * 128, nb = blockIdx.x * 128;
    const int lr = lane >> 2, lc = lane & 3;
    const uint32_t sb = smem_u32(smg);

    const int arow = (lane & 7) + ((lane >> 3) & 1) * 8;
    const int acol = (lane >> 4) * 8;
    const int brow = (lane & 7) + (lane >> 4) * 8;
    const int bcol = ((lane >> 3) & 1) * 8;

    uint32_t a_off[2], b_off[4];
#pragma unroll
    for (int mt = 0; mt < 2; mt++)
        a_off[mt] = (uint32_t)((wm * 32 + mt * 16 + arow) * PADH + acol) * 2;
#pragma unroll
    for (int p = 0; p < 4; p++)
        b_off[p] = (uint32_t)(128 * PADH + (wn * 64 + p * 16 + brow) * PADH + bcol) * 2;

    float acc[2][8][4];
#pragma unroll
    for (int i = 0; i < 2; i++)
#pragma unroll
        for (int j = 0; j < 8; j++)
#pragma unroll
            for (int c = 0; c < 4; c++) acc[i][j][c] = 0.0f;

    // cp.async one 128x64-half chunk pair: 8 CP16 per thread.
    const int cr = tid >> 3, cc = tid & 7;    // rows 0..31, chunks 0..7
    auto issue = [&](int kt, int s) {
        const int k0 = kt * 64;
        uint32_t base = sb + (uint32_t)s * GST_H * 2;
#pragma unroll
        for (int t = 0; t < 8; t++) {
            int r = cr + (t >> 1) * 32;       // 0..127
            const __half* src = (t & 1) ? W + (size_t)(nb + r) * DIM + k0 + cc * 8
                                        : X + (size_t)(mb + r) * DIM + k0 + cc * 8;
            uint32_t dst = base + ((t & 1) ? (uint32_t)(128 * PADH * 2) : 0u) +
                           (uint32_t)(r * PADH + cc * 8) * 2;
            CP16(dst, src);
        }
        CP_COMMIT();
    };

    issue(0, 0); issue(1, 1);
    int st = 0, st2 = 2;                      // stage of kt, stage of kt+2
    for (int kt = 0; kt < 8; kt++) {
        if (kt < 7) CP_WAIT1(); else CP_WAIT0();
        __syncthreads();
        if (kt + 2 < 8) issue(kt + 2, st2);   // post-barrier (3-stage safety)

        const uint32_t sbs = sb + (uint32_t)st * GST_H * 2;
#pragma unroll
        for (int ks = 0; ks < 4; ks++) {
            const uint32_t kkb = (uint32_t)(ks * 16) * 2;
            uint32_t a[2][4], b[8][2];
#pragma unroll
            for (int mt = 0; mt < 2; mt++)
                LDSM4(a[mt][0], a[mt][1], a[mt][2], a[mt][3],
                      sbs + a_off[mt] + kkb);
#pragma unroll
            for (int p = 0; p < 4; p++)
                LDSM4(b[2 * p][0], b[2 * p][1], b[2 * p + 1][0], b[2 * p + 1][1],
                      sbs + b_off[p] + kkb);
#pragma unroll
            for (int mt = 0; mt < 2; mt++)
#pragma unroll
                for (int nt = 0; nt < 8; nt++)
                    mma_f16(acc[mt][nt], a[mt], b[nt]);
        }
        st = (st == 2) ? 0 : st + 1;
        st2 = (st2 == 2) ? 0 : st2 + 1;
    }
    __syncthreads();

#pragma unroll
    for (int mt = 0; mt < 2; mt++) {
        int r0 = mb + wm * 32 + mt * 16 + lr;
#pragma unroll
        for (int nt = 0; nt < 8; nt++) {
            int c0 = nb + wn * 64 + nt * 8 + 2 * lc;
            if (Yf) {
                *(float2*)(Yf + (size_t)r0 * DIM + c0) =
                    make_float2(acc[mt][nt][0], acc[mt][nt][1]);
                *(float2*)(Yf + (size_t)(r0 + 8) * DIM + c0) =
                    make_float2(acc[mt][nt][2], acc[mt][nt][3]);
            } else {
                *(uint32_t*)(Yh + (size_t)r0 * DIM + c0) =
                    pack2(acc[mt][nt][0] * escale, acc[mt][nt][1] * escale);
                *(uint32_t*)(Yh + (size_t)(r0 + 8) * DIM + c0) =
                    pack2(acc[mt][nt][2] * escale, acc[mt][nt][3] * escale);
            }
        }
    }
}

__global__ __launch_bounds__(256, 2) void qkv_gemm() {
    const int z = blockIdx.z;
    __half* Y = (z == 0) ? g_q : (z == 1) ? g_k : g_v;
    float es = (z == 0) ? SCALE : (z == 1) ? LOG2E : 1.0f;
    gemm_body(hx, hw + (size_t)z * DIM * DIM, Y, nullptr, es);
}

__global__ __launch_bounds__(256, 2) void out_gemm(float* __restrict__ out) {
    gemm_body(g_o, hw + 3 * (size_t)DIM * DIM, nullptr, out, 1.0f);
}

// ---------------------------------------------------------------------------
// Flash attention, fp16 m16n8k16, q-tile 128 per 256-thr CTA, 3-stage
// cp.async over 128-key stages (16 iters, ONE barrier each, two 64-key
// sub-halves computed barrier-free). Q in stage-2 region during prologue
// only; p = ex2.approx.f16x2; l via hoisted ones-column mma.
// ---------------------------------------------------------------------------
#define PADA 72
#define AKS_H (128 * PADA)                    // K halves per stage (9216)
#define ASTAGE_H (2 * AKS_H)                  // K + V per stage (36864 B)
#define ATTN_SMEM (3 * ASTAGE_H * 2)          // 110592 B -> 2 CTAs/SM

__global__ __launch_bounds__(256, 2) void attn_f16() {
    extern __shared__ __half smh[];
    const int tid = threadIdx.x, lane = tid & 31, wid = tid >> 5;
    const int lr = lane >> 2, lc = lane & 3;
    const int bh = blockIdx.y, b_ = bh >> 3, h_ = bh & 7;
    const int q0 = blockIdx.x * 128;
    const uint32_t sb = smem_u32(smh);

    const __half* Qg = g_q + (size_t)b_ * L * DIM + h_ * 64;
    const __half* Kg = g_k + (size_t)b_ * L * DIM + h_ * 64;
    const __half* Vg = g_v + (size_t)b_ * L * DIM + h_ * 64;

    const int arow = (lane & 7) + ((lane >> 3) & 1) * 8;
    const int acol = (lane >> 4) * 8;
    const int brow = (lane & 7) + (lane >> 4) * 8;
    const int bcol = ((lane >> 3) & 1) * 8;

    uint32_t k_off[4];
#pragma unroll
    for (int p = 0; p < 4; p++)
        k_off[p] = (uint32_t)((p * 16 + brow) * PADA + bcol) * 2;
    const uint32_t v_roff = (uint32_t)(arow * PADA) * 2;
    const uint32_t v_l_off = (uint32_t)((lane & 15) * PADA + 64) * 2;

    // cp.async one 128-key K/V stage: 8 CP16 per thread.
    const int ar = tid >> 3, ac = tid & 7;    // rows 0..31, chunks 0..7
    auto issue = [&](int t, int s) {
        const int k0g = t * 128;
        uint32_t base = sb + (uint32_t)s * ASTAGE_H * 2;
#pragma unroll
        for (int u = 0; u < 4; u++) {
            int r = ar + u * 32;              // 0..127
            CP16(base + (uint32_t)(r * PADA + ac * 8) * 2,
                 Kg + (size_t)(k0g + r) * DIM + ac * 8);
            CP16(base + (uint32_t)(AKS_H + r * PADA + ac * 8) * 2,
                 Vg + (size_t)(k0g + r) * DIM + ac * 8);
        }
        CP_COMMIT();
    };

    issue(0, 0); issue(1, 1);

    // Stage Q [128][64] into the stage-2 K region (first cp.async write to
    // stage 2 happens at iter-0's post-barrier issue — after aq extraction).
    __half* Qs = smh + 2 * ASTAGE_H;
#pragma unroll
    for (int t = 0; t < 4; t++) {
        int idx = tid + t * 256;              // 0..1023
        int r = idx >> 3, c = idx & 7;
        *(uint4*)&Qs[r * PADA + c * 8] =
            *(const uint4*)(Qg + (size_t)(q0 + r) * DIM + c * 8);
    }
    // Ones-column init in V padding, all 3 stages (cols 64..71 — never
    // touched by cp.async; persist across stage reuse).
    {
#pragma unroll
        for (int t = 0; t < 2; t++) {
            int idx = tid + t * 256;          // 0..511, need 384
            if (idx < 3 * 128) {
                int s_ = idx >> 7, r = idx & 127;
                __half* p = smh + s_ * ASTAGE_H + AKS_H + r * PADA + 64;
                *(uint4*)p = make_uint4(0x00003C00u, 0u, 0u, 0u);
            }
        }
    }
    __syncthreads();
    uint32_t aq[4][4];
    {
        uint32_t qbase = sb + (uint32_t)(2 * ASTAGE_H) * 2 +
                         (uint32_t)((wid * 16 + arow) * PADA + acol) * 2;
#pragma unroll
        for (int ks = 0; ks < 4; ks++)
            LDSM4(aq[ks][0], aq[ks][1], aq[ks][2], aq[ks][3],
                  qbase + (uint32_t)(ks * 16) * 2);
    }
    // Hoist the (constant) ones-column fragments for the l mma.
    uint32_t bl[2];
    LDSM2T(bl[0], bl[1], sb + (uint32_t)AKS_H * 2 + v_l_off);
    __syncthreads();                          // stage-2 region free hereafter

    float o[8][4], o_l[4];
#pragma unroll
    for (int nt = 0; nt < 8; nt++)
#pragma unroll
        for (int c = 0; c < 4; c++) o[nt][c] = 0.0f;
#pragma unroll
    for (int c = 0; c < 4; c++) o_l[c] = 0.0f;

    const int row0 = q0 + wid * 16 + lr;
    const int row1 = row0 + 8;

    int st = 0, st2 = 2;
    for (int t = 0; t < 16; t++) {
        if (t < 15) CP_WAIT1(); else CP_WAIT0();
        __syncthreads();
        if (t + 2 < 16) issue(t + 2, st2);    // post-barrier (3-stage safety)

        const uint32_t sbs = sb + (uint32_t)st * ASTAGE_H * 2;

#pragma unroll
        for (int hf = 0; hf < 2; hf++) {
            const uint32_t hoff = (uint32_t)(hf * 64 * PADA) * 2;
            const int k0g = t * 128 + hf * 64;

            // S = Q @ K^T : 16 q x 64 keys per warp.
            float s[8][4];
#pragma unroll
            for (int nt = 0; nt < 8; nt++)
#pragma unroll
                for (int c = 0; c < 4; c++) s[nt][c] = 0.0f;
#pragma unroll
            for (int ks = 0; ks < 4; ks++) {
                const uint32_t kkb = (uint32_t)(ks * 16) * 2;
                uint32_t bk[8][2];
#pragma unroll
                for (int p = 0; p < 4; p++)
                    LDSM4(bk[2 * p][0], bk[2 * p][1],
                          bk[2 * p + 1][0], bk[2 * p + 1][1],
                          sbs + hoff + k_off[p] + kkb);
#pragma unroll
                for (int nt = 0; nt < 8; nt++) mma_f16(s[nt], aq[ks], bk[nt]);
            }

            // p = 2^s; diag mask only when window hits this warp's rows.
            uint32_t pk[8][2];
#pragma unroll
            for (int nt = 0; nt < 8; nt++) {
                pk[nt][0] = h2ex2(pack2(s[nt][0], s[nt][1]));
                pk[nt][1] = h2ex2(pack2(s[nt][2], s[nt][3]));
            }
            if ((unsigned)(row0 - k0g) < 64u || (unsigned)(row1 - k0g) < 64u) {
#pragma unroll
                for (int nt = 0; nt < 8; nt++) {
                    int key = k0g + nt * 8 + 2 * lc;
                    if (key == row0) pk[nt][0] &= 0xFFFF0000u;
                    if (key + 1 == row0) pk[nt][0] &= 0x0000FFFFu;
                    if (key == row1) pk[nt][1] &= 0xFFFF0000u;
                    if (key + 1 == row1) pk[nt][1] &= 0x0000FFFFu;
                }
            }

            // O += P @ V; l += P @ ones.
#pragma unroll
            for (int ksl = 0; ksl < 4; ksl++) {
                uint32_t ap[4];
                ap[0] = pk[2 * ksl][0];
                ap[1] = pk[2 * ksl][1];
                ap[2] = pk[2 * ksl + 1][0];
                ap[3] = pk[2 * ksl + 1][1];

                const uint32_t vb = sbs + (uint32_t)AKS_H * 2 + hoff +
                                    (uint32_t)(ksl * 16 * PADA) * 2;
                uint32_t bv[8][2];
#pragma unroll
                for (int p = 0; p < 4; p++)
                    LDSM4T(bv[2 * p][0], bv[2 * p][1],
                           bv[2 * p + 1][0], bv[2 * p + 1][1],
                           vb + v_roff + (uint32_t)acol * 2 +
                           (uint32_t)(p * 16) * 2);
#pragma unroll
                for (int nt = 0; nt < 8; nt++) mma_f16(o[nt], ap, bv[nt]);
                mma_f16(o_l, ap, bl);
            }
        }
        st = (st == 2) ? 0 : st + 1;
        st2 = (st2 == 2) ? 0 : st2 + 1;
    }

    // Epilogue: l complete per warp. l in col 64 -> lc==0 lanes of each quad.
    float l0 = __shfl_sync(0xffffffffu, o_l[0], lane & 28);
    float l1 = __shfl_sync(0xffffffffu, o_l[2], lane & 28);
    const float inv0 = 1.0f / l0, inv1 = 1.0f / l1;
    __half* Og = g_o + ((size_t)b_ * L) * DIM + h_ * 64;
#pragma unroll
    for (int nt = 0; nt < 8; nt++) {
        int c0 = nt * 8 + 2 * lc;
        *(uint32_t*)(Og + (size_t)row0 * DIM + c0) =
            pack2(o[nt][0] * inv0, o[nt][1] * inv0);
        *(uint32_t*)(Og + (size_t)row1 * DIM + c0) =
            pack2(o[nt][2] * inv1, o[nt][3] * inv1);
    }
}

// ---------------------------------------------------------------------------
extern "C" void kernel_launch(void* const* d_in, const int* in_sizes, int n_in,
                              void* d_out, int out_size) {
    const float* x  = (const float*)d_in[0];
    const float* wq = (const float*)d_in[1];
    const float* wk = (const float*)d_in[2];
    const float* wv = (const float*)d_in[3];
    const float* wo = (const float*)d_in[4];
    float* out = (float*)d_out;

    cudaFuncSetAttribute(qkv_gemm, cudaFuncAttributeMaxDynamicSharedMemorySize,
                         GEMM_SMEM);
    cudaFuncSetAttribute(out_gemm, cudaFuncAttributeMaxDynamicSharedMemorySize,
                         GEMM_SMEM);
    cudaFuncSetAttribute(attn_f16, cudaFuncAttributeMaxDynamicSharedMemorySize,
                         ATTN_SMEM);
    cudaFuncSetAttribute(qkv_gemm, cudaFuncAttributePreferredSharedMemoryCarveout, 100);
    cudaFuncSetAttribute(out_gemm, cudaFuncAttributePreferredSharedMemoryCarveout, 100);
    cudaFuncSetAttribute(attn_f16, cudaFuncAttributePreferredSharedMemoryCarveout, 100);

    cvt_all<<<dim3(128, 5), 256>>>(x, wq, wk, wv, wo);
    qkv_gemm<<<dim3(4, 64, 3), 256, GEMM_SMEM>>>();
    attn_f16<<<dim3(L / 128, B * H), 256, ATTN_SMEM>>>();
    out_gemm<<<dim3(4, 64), 256, GEMM_SMEM>>>(out);
}

// round 16
// speedup vs baseline: 1.0371x; 1.0371x over previous
#include <cuda_runtime.h>
#include <cuda_fp16.h>
#include <cstdint>

#define B 4
#define L 2048
#define DIM 512
#define H 8
#define D 64
#define M_TOTAL (B * L)
#define SCALE 0.125f
#define LOG2E 1.44269504088896f

// fp16 scratch (allocation-free rule: __device__ globals).
__device__ __half hx[M_TOTAL * DIM];
__device__ __half hw[4 * DIM * DIM];         // wq, wk, wv, wo
__device__ __half g_q[M_TOTAL * DIM];        // pre-scaled by SCALE
__device__ __half g_k[M_TOTAL * DIM];        // pre-scaled by log2(e)
__device__ __half g_v[M_TOTAL * DIM];
__device__ __half g_o[M_TOTAL * DIM];

__device__ __forceinline__ uint32_t pack2(float a, float b) {
    __half2 h = __floats2half2_rn(a, b);
    return *(uint32_t*)&h;
}
__device__ __forceinline__ uint32_t h2ex2(uint32_t x) {
    uint32_t r;
    asm("ex2.approx.f16x2 %0, %1;" : "=r"(r) : "r"(x));
    return r;
}

// fp32-accum mma (projections, PV).
__device__ __forceinline__ void mma_f16(float* d, const uint32_t* a,
                                        const uint32_t* b) {
    asm volatile(
        "mma.sync.aligned.m16n8k16.row.col.f32.f16.f16.f32 "
        "{%0,%1,%2,%3}, {%4,%5,%6,%7}, {%8,%9}, {%0,%1,%2,%3};"
        : "+f"(d[0]), "+f"(d[1]), "+f"(d[2]), "+f"(d[3])
        : "r"(a[0]), "r"(a[1]), "r"(a[2]), "r"(a[3]), "r"(b[0]), "r"(b[1]));
}

// fp16-accum mma (S = QK^T only: 4-step chain, |s| small, 2x rate, and the
// packed-D layout == A-fragment layout -> ex2 applies directly).
__device__ __forceinline__ void mma_s16(uint32_t* d, const uint32_t* a,
                                        const uint32_t* b) {
    asm volatile(
        "mma.sync.aligned.m16n8k16.row.col.f16.f16.f16.f16 "
        "{%0,%1}, {%2,%3,%4,%5}, {%6,%7}, {%0,%1};"
        : "+r"(d[0]), "+r"(d[1])
        : "r"(a[0]), "r"(a[1]), "r"(a[2]), "r"(a[3]), "r"(b[0]), "r"(b[1]));
}

__device__ __forceinline__ uint32_t smem_u32(const void* p) {
    uint32_t a;
    asm("{ .reg .u64 t; cvta.to.shared.u64 t, %1; cvt.u32.u64 %0, t; }"
        : "=r"(a) : "l"(p));
    return a;
}

#define LDSM4(d0, d1, d2, d3, a) \
    asm volatile("ldmatrix.sync.aligned.m8n8.x4.shared.b16 {%0,%1,%2,%3}, [%4];" \
                 : "=r"(d0), "=r"(d1), "=r"(d2), "=r"(d3) : "r"(a))
#define LDSM4T(d0, d1, d2, d3, a) \
    asm volatile("ldmatrix.sync.aligned.m8n8.x4.trans.shared.b16 {%0,%1,%2,%3}, [%4];" \
                 : "=r"(d0), "=r"(d1), "=r"(d2), "=r"(d3) : "r"(a))
#define LDSM2T(d0, d1, a) \
    asm volatile("ldmatrix.sync.aligned.m8n8.x2.trans.shared.b16 {%0,%1}, [%2];" \
                 : "=r"(d0), "=r"(d1) : "r"(a))

#define CP16(dst, src) \
    asm volatile("cp.async.cg.shared.global [%0], [%1], 16;" \
                 :: "r"(dst), "l"(src) : "memory")
#define CP_COMMIT() asm volatile("cp.async.commit_group;" ::: "memory")
#define CP_WAIT2() asm volatile("cp.async.wait_group 2;" ::: "memory")
#define CP_WAIT1() asm volatile("cp.async.wait_group 1;" ::: "memory")
#define CP_WAIT0() asm volatile("cp.async.wait_group 0;" ::: "memory")

// ---------------------------------------------------------------------------
// fp32 -> fp16 conversion, one launch (blockIdx.y selects tensor).
// ---------------------------------------------------------------------------
__global__ void cvt_all(const float* __restrict__ x,  const float* __restrict__ wq,
                        const float* __restrict__ wk, const float* __restrict__ wv,
                        const float* __restrict__ wo) {
    const int sel = blockIdx.y;
    const float* src;
    __half* dst;
    int n4;
    if (sel == 0) { src = x;  dst = hx;                 n4 = M_TOTAL * DIM / 4; }
    else if (sel == 1) { src = wq; dst = hw;                n4 = DIM * DIM / 4; }
    else if (sel == 2) { src = wk; dst = hw + DIM * DIM;    n4 = DIM * DIM / 4; }
    else if (sel == 3) { src = wv; dst = hw + 2 * DIM * DIM; n4 = DIM * DIM / 4; }
    else { src = wo; dst = hw + 3 * DIM * DIM; n4 = DIM * DIM / 4; }
    int i = blockIdx.x * blockDim.x + threadIdx.x;
    int stride = gridDim.x * blockDim.x;
    for (; i < n4; i += stride) {
        float4 v = ((const float4*)src)[i];
        ((__half2*)dst)[2 * i] = __floats2half2_rn(v.x, v.y);
        ((__half2*)dst)[2 * i + 1] = __floats2half2_rn(v.z, v.w);
    }
}

// ---------------------------------------------------------------------------
// GEMM: Y = X @ W.T, fp16 m16n8k16, f32 accum, ldmatrix, 4-stage cp.async,
// single barrier + early prefetch (R14 proven config). escale folds
// SCALE / log2e into Q / K at the single fp16 rounding.
// ---------------------------------------------------------------------------
#define PADH 40                               // halves per row (80 B)
#define GST_H (2 * 128 * PADH)                // A+B halves per stage (10240)
#define GEMM_SMEM (4 * GST_H * 2)             // 81920 B -> 2 CTAs/SM

__device__ __forceinline__ void gemm_body(const __half* __restrict__ X,
                                          const __half* __restrict__ W,
                                          __half* __restrict__ Yh,
                                          float* __restrict__ Yf,
                                          float escale) {
    extern __shared__ __half smg[];
    const int tid = threadIdx.x, lane = tid & 31, wid = tid >> 5;
    const int wm = wid & 3, wn = wid >> 2;
    const int mb = blockIdx.y * 128, nb = blockIdx.x * 128;
    const int lr = lane >> 2, lc = lane & 3;
    const uint32_t sb = smem_u32(smg);

    const int arow = (lane & 7) + ((lane >> 3) & 1) * 8;
    const int acol = (lane >> 4) * 8;
    const int brow = (lane & 7) + (lane >> 4) * 8;
    const int bcol = ((lane >> 3) & 1) * 8;

    uint32_t a_off[2], b_off[4];
#pragma unroll
    for (int mt = 0; mt < 2; mt++)
        a_off[mt] = (uint32_t)((wm * 32 + mt * 16 + arow) * PADH + acol) * 2;
#pragma unroll
    for (int p = 0; p < 4; p++)
        b_off[p] = (uint32_t)(128 * PADH + (wn * 64 + p * 16 + brow) * PADH + bcol) * 2;

    float acc[2][8][4];
#pragma unroll
    for (int i = 0; i < 2; i++)
#pragma unroll
        for (int j = 0; j < 8; j++)
#pragma unroll
            for (int c = 0; c < 4; c++) acc[i][j][c] = 0.0f;

    const int cr = tid >> 2, cc = tid & 3;
    auto issue = [&](int kt, int s) {
        const int k0 = kt * 32;
        uint32_t base = sb + (uint32_t)s * GST_H * 2;
#pragma unroll
        for (int t = 0; t < 4; t++) {
            int r = cr + (t >> 1) * 64;
            const __half* src = (t & 1) ? W + (size_t)(nb + r) * DIM + k0 + cc * 8
                                        : X + (size_t)(mb + r) * DIM + k0 + cc * 8;
            uint32_t dst = base + ((t & 1) ? (uint32_t)(128 * PADH * 2) : 0u) +
                           (uint32_t)(r * PADH + cc * 8) * 2;
            CP16(dst, src);
        }
        CP_COMMIT();
    };

    issue(0, 0); issue(1, 1);
    for (int kt = 0; kt < 16; kt++) {
        if (kt + 2 < 16) issue(kt + 2, (kt + 2) & 3);   // early prefetch
        if (kt < 14) CP_WAIT2();
        else if (kt == 14) CP_WAIT1();
        else CP_WAIT0();
        __syncthreads();

        const uint32_t sbs = sb + (uint32_t)(kt & 3) * GST_H * 2;
#pragma unroll
        for (int ks = 0; ks < 2; ks++) {
            const uint32_t kkb = (uint32_t)(ks * 16) * 2;
            uint32_t a[2][4], b[8][2];
#pragma unroll
            for (int mt = 0; mt < 2; mt++)
                LDSM4(a[mt][0], a[mt][1], a[mt][2], a[mt][3],
                      sbs + a_off[mt] + kkb);
#pragma unroll
            for (int p = 0; p < 4; p++)
                LDSM4(b[2 * p][0], b[2 * p][1], b[2 * p + 1][0], b[2 * p + 1][1],
                      sbs + b_off[p] + kkb);
#pragma unroll
            for (int mt = 0; mt < 2; mt++)
#pragma unroll
                for (int nt = 0; nt < 8; nt++)
                    mma_f16(acc[mt][nt], a[mt], b[nt]);
        }
    }
    __syncthreads();

#pragma unroll
    for (int mt = 0; mt < 2; mt++) {
        int r0 = mb + wm * 32 + mt * 16 + lr;
#pragma unroll
        for (int nt = 0; nt < 8; nt++) {
            int c0 = nb + wn * 64 + nt * 8 + 2 * lc;
            if (Yf) {
                *(float2*)(Yf + (size_t)r0 * DIM + c0) =
                    make_float2(acc[mt][nt][0], acc[mt][nt][1]);
                *(float2*)(Yf + (size_t)(r0 + 8) * DIM + c0) =
                    make_float2(acc[mt][nt][2], acc[mt][nt][3]);
            } else {
                *(uint32_t*)(Yh + (size_t)r0 * DIM + c0) =
                    pack2(acc[mt][nt][0] * escale, acc[mt][nt][1] * escale);
                *(uint32_t*)(Yh + (size_t)(r0 + 8) * DIM + c0) =
                    pack2(acc[mt][nt][2] * escale, acc[mt][nt][3] * escale);
            }
        }
    }
}

__global__ __launch_bounds__(256, 2) void qkv_gemm() {
    const int z = blockIdx.z;
    __half* Y = (z == 0) ? g_q : (z == 1) ? g_k : g_v;
    float es = (z == 0) ? SCALE : (z == 1) ? LOG2E : 1.0f;
    gemm_body(hx, hw + (size_t)z * DIM * DIM, Y, nullptr, es);
}

__global__ __launch_bounds__(256, 2) void out_gemm(float* __restrict__ out) {
    gemm_body(g_o, hw + 3 * (size_t)DIM * DIM, nullptr, out, 1.0f);
}

// ---------------------------------------------------------------------------
// Flash attention (R14 shape), with S = QK^T computed in fp16-accum mma
// (2x tensor rate; packed D == A layout so ex2 applies directly, no pack2).
// q-tile 128 per 256-thr CTA (occ 2), 4-stage cp.async over 64-key tiles,
// single barrier + early prefetch, l via hoisted ones-column mma.
// ---------------------------------------------------------------------------
#define PADA 72
#define KS_H (64 * PADA)                      // 4608 halves per K tile
#define ASTAGE_H (2 * KS_H)                   // K + V per stage (18432 B)
#define ATTN_SMEM (4 * ASTAGE_H * 2)          // 73728 B -> 2 CTAs/SM

__global__ __launch_bounds__(256, 2) void attn_f16() {
    extern __shared__ __half smh[];
    const int tid = threadIdx.x, lane = tid & 31, wid = tid >> 5;
    const int lr = lane >> 2, lc = lane & 3;
    const int bh = blockIdx.y, b_ = bh >> 3, h_ = bh & 7;
    const int q0 = blockIdx.x * 128;
    const uint32_t sb = smem_u32(smh);

    const __half* Qg = g_q + (size_t)b_ * L * DIM + h_ * 64;
    const __half* Kg = g_k + (size_t)b_ * L * DIM + h_ * 64;
    const __half* Vg = g_v + (size_t)b_ * L * DIM + h_ * 64;

    const int arow = (lane & 7) + ((lane >> 3) & 1) * 8;
    const int acol = (lane >> 4) * 8;
    const int brow = (lane & 7) + (lane >> 4) * 8;
    const int bcol = ((lane >> 3) & 1) * 8;

    uint32_t k_off[4];
#pragma unroll
    for (int p = 0; p < 4; p++)
        k_off[p] = (uint32_t)((p * 16 + brow) * PADA + bcol) * 2;
    const uint32_t v_roff = (uint32_t)(arow * PADA) * 2;
    const uint32_t v_l_off = (uint32_t)((lane & 15) * PADA + 64) * 2;

    // cp.async one 64-key K/V stage: 4 CP16 per thread.
    const int ar = tid >> 3, ac = tid & 7;
    auto issue = [&](int t, int s) {
        const int k0g = t * 64;
        uint32_t base = sb + (uint32_t)s * ASTAGE_H * 2;
#pragma unroll
        for (int u = 0; u < 2; u++) {
            int r = ar + u * 32;
            CP16(base + (uint32_t)(r * PADA + ac * 8) * 2,
                 Kg + (size_t)(k0g + r) * DIM + ac * 8);
            CP16(base + (uint32_t)(KS_H + r * PADA + ac * 8) * 2,
                 Vg + (size_t)(k0g + r) * DIM + ac * 8);
        }
        CP_COMMIT();
    };

    issue(0, 0); issue(1, 1);

    // Stage Q [128][64] into the stage-3 region (cols 0..63; pads free).
    __half* Qs = smh + 3 * ASTAGE_H;
#pragma unroll
    for (int t = 0; t < 4; t++) {
        int idx = tid + t * 256;
        int r = idx >> 3, c = idx & 7;
        *(uint4*)&Qs[r * PADA + c * 8] =
            *(const uint4*)(Qg + (size_t)(q0 + r) * DIM + c * 8);
    }
    // Ones-column init in V padding, all 4 stages (cols 64..71 — disjoint
    // from cp.async bytes AND from Q staging).
    {
        int s_ = tid >> 6, r = tid & 63;
        __half* p = smh + s_ * ASTAGE_H + KS_H + r * PADA + 64;
        *(uint4*)p = make_uint4(0x00003C00u, 0u, 0u, 0u);
    }
    __syncthreads();
    uint32_t aq[4][4];
    {
        uint32_t qbase = sb + (uint32_t)(3 * ASTAGE_H) * 2 +
                         (uint32_t)((wid * 16 + arow) * PADA + acol) * 2;
#pragma unroll
        for (int ks = 0; ks < 4; ks++)
            LDSM4(aq[ks][0], aq[ks][1], aq[ks][2], aq[ks][3],
                  qbase + (uint32_t)(ks * 16) * 2);
    }
    // Hoist the (constant) ones-column fragments for the l mma.
    uint32_t bl[2];
    LDSM2T(bl[0], bl[1], sb + (uint32_t)KS_H * 2 + v_l_off);
    __syncthreads();                          // stage-3 region free hereafter

    float o[8][4], o_l[4];
#pragma unroll
    for (int nt = 0; nt < 8; nt++)
#pragma unroll
        for (int c = 0; c < 4; c++) o[nt][c] = 0.0f;
#pragma unroll
    for (int c = 0; c < 4; c++) o_l[c] = 0.0f;

    const int row0 = q0 + wid * 16 + lr;
    const int row1 = row0 + 8;

    for (int t = 0; t < 32; t++) {
        if (t + 2 < 32) issue(t + 2, (t + 2) & 3);      // early prefetch
        if (t < 30) CP_WAIT2();
        else if (t == 30) CP_WAIT1();
        else CP_WAIT0();
        __syncthreads();

        const uint32_t sbs = sb + (uint32_t)(t & 3) * ASTAGE_H * 2;
        const int k0g = t * 64;

        // S = Q @ K^T in fp16 accum: 16 q x 64 keys per warp. Packed D regs
        // sk[nt] = {s0,s1},{s2,s3} — exactly the A-fragment layout.
        uint32_t sk[8][2];
#pragma unroll
        for (int nt = 0; nt < 8; nt++) { sk[nt][0] = 0u; sk[nt][1] = 0u; }
#pragma unroll
        for (int ks = 0; ks < 4; ks++) {
            const uint32_t kkb = (uint32_t)(ks * 16) * 2;
            uint32_t bk[8][2];
#pragma unroll
            for (int p = 0; p < 4; p++)
                LDSM4(bk[2 * p][0], bk[2 * p][1],
                      bk[2 * p + 1][0], bk[2 * p + 1][1],
                      sbs + k_off[p] + kkb);
#pragma unroll
            for (int nt = 0; nt < 8; nt++) mma_s16(sk[nt], aq[ks], bk[nt]);
        }

        // p = 2^s directly on the packed accumulators; diag mask only when
        // this key window intersects this warp's rows (1 of 32 iters).
        uint32_t pk[8][2];
#pragma unroll
        for (int nt = 0; nt < 8; nt++) {
            pk[nt][0] = h2ex2(sk[nt][0]);
            pk[nt][1] = h2ex2(sk[nt][1]);
        }
        if ((unsigned)(row0 - k0g) < 64u || (unsigned)(row1 - k0g) < 64u) {
#pragma unroll
            for (int nt = 0; nt < 8; nt++) {
                int key = k0g + nt * 8 + 2 * lc;
                if (key == row0) pk[nt][0] &= 0xFFFF0000u;
                if (key + 1 == row0) pk[nt][0] &= 0x0000FFFFu;
                if (key == row1) pk[nt][1] &= 0xFFFF0000u;
                if (key + 1 == row1) pk[nt][1] &= 0x0000FFFFu;
            }
        }

        // O += P @ V (fp32 accum); l += P @ ones.
#pragma unroll
        for (int ksl = 0; ksl < 4; ksl++) {
            uint32_t ap[4];
            ap[0] = pk[2 * ksl][0];
            ap[1] = pk[2 * ksl][1];
            ap[2] = pk[2 * ksl + 1][0];
            ap[3] = pk[2 * ksl + 1][1];

            const uint32_t vb = sbs + (uint32_t)KS_H * 2 +
                                (uint32_t)(ksl * 16 * PADA) * 2;
            uint32_t bv[8][2];
#pragma unroll
            for (int p = 0; p < 4; p++)
                LDSM4T(bv[2 * p][0], bv[2 * p][1],
                       bv[2 * p + 1][0], bv[2 * p + 1][1],
                       vb + v_roff + (uint32_t)acol * 2 +
                       (uint32_t)(p * 16) * 2);
#pragma unroll
            for (int nt = 0; nt < 8; nt++) mma_f16(o[nt], ap, bv[nt]);
            mma_f16(o_l, ap, bl);
        }
    }

    // Epilogue: l complete per warp. l in col 64 -> lc==0 lanes of each quad.
    float l0 = __shfl_sync(0xffffffffu, o_l[0], lane & 28);
    float l1 = __shfl_sync(0xffffffffu, o_l[2], lane & 28);
    const float inv0 = 1.0f / l0, inv1 = 1.0f / l1;
    __half* Og = g_o + ((size_t)b_ * L) * DIM + h_ * 64;
#pragma unroll
    for (int nt = 0; nt < 8; nt++) {
        int c0 = nt * 8 + 2 * lc;
        *(uint32_t*)(Og + (size_t)row0 * DIM + c0) =
            pack2(o[nt][0] * inv0, o[nt][1] * inv0);
        *(uint32_t*)(Og + (size_t)row1 * DIM + c0) =
            pack2(o[nt][2] * inv1, o[nt][3] * inv1);
    }
}

// ---------------------------------------------------------------------------
extern "C" void kernel_launch(void* const* d_in, const int* in_sizes, int n_in,
                              void* d_out, int out_size) {
    const float* x  = (const float*)d_in[0];
    const float* wq = (const float*)d_in[1];
    const float* wk = (const float*)d_in[2];
    const float* wv = (const float*)d_in[3];
    const float* wo = (const float*)d_in[4];
    float* out = (float*)d_out;

    cudaFuncSetAttribute(qkv_gemm, cudaFuncAttributeMaxDynamicSharedMemorySize,
                         GEMM_SMEM);
    cudaFuncSetAttribute(out_gemm, cudaFuncAttributeMaxDynamicSharedMemorySize,
                         GEMM_SMEM);
    cudaFuncSetAttribute(attn_f16, cudaFuncAttributeMaxDynamicSharedMemorySize,
                         ATTN_SMEM);
    cudaFuncSetAttribute(qkv_gemm, cudaFuncAttributePreferredSharedMemoryCarveout, 100);
    cudaFuncSetAttribute(out_gemm, cudaFuncAttributePreferredSharedMemoryCarveout, 100);
    cudaFuncSetAttribute(attn_f16, cudaFuncAttributePreferredSharedMemoryCarveout, 100);

    cvt_all<<<dim3(128, 5), 256>>>(x, wq, wk, wv, wo);
    qkv_gemm<<<dim3(4, 64, 3), 256, GEMM_SMEM>>>();
    attn_f16<<<dim3(L / 128, B * H), 256, ATTN_SMEM>>>();
    out_gemm<<<dim3(4, 64), 256, GEMM_SMEM>>>(out);
}